// round 15
// baseline (speedup 1.0000x reference)
#include <cuda_runtime.h>
#include <cuda_fp16.h>
#include <cstdint>

// Problem constants (fixed by the dataset)
#define Qn 20000
#define Gn 20000
#define Hn 32          // neighbors per query
#define Kn 15          // kernel points
#define Cn 128
#define On 128
#define KC (Kn * Cn)   // 1920

// GEMM tiling (fp16 single-chain)
#define BM 64
#define BN 128
#define BK 64
#define NCH (KC / BK)          // 30 chunks
#define LDT 144                // padded row stride in bytes (64 fp16 + 16B pad)
#define A_TILE_B (BM * LDT)    // 9216
#define B_TILE_B (BN * LDT)    // 18432
#define OFF_B    A_TILE_B
#define STAGE_B  (A_TILE_B + B_TILE_B)   // 27648
#define SMEM_TOTAL (2 * STAGE_B)          // 55296 (phase-1 area overlaid)

#define P1_WARP_B 6144         // per-warp phase-1 smem carve (8 warps = 49152)

// Scratch (device globals per harness rules)
__device__ __align__(256) __half g_P [(size_t)Qn * KC];   // 76.8 MB (L2-hot per CTA)
__device__ __align__(256) __half g_Wt[(size_t)On * KC];   // Wt[n][k], 4.9 MB

// ---------------------------------------------------------------------------
// PTX helpers (sm_80-era only: compile on base compute_103 target)
// ---------------------------------------------------------------------------
__device__ __forceinline__ uint32_t smem_u32(const void* p) {
    uint32_t a;
    asm("{ .reg .u64 t; cvta.to.shared.u64 t, %1; cvt.u32.u64 %0, t; }" : "=r"(a) : "l"(p));
    return a;
}
__device__ __forceinline__ void cp16(uint32_t dst, const void* src, int sz) {
    asm volatile("cp.async.cg.shared.global [%0], [%1], 16, %2;"
                 :: "r"(dst), "l"(src), "r"(sz) : "memory");
}
#define CP_COMMIT() asm volatile("cp.async.commit_group;" ::: "memory")
#define CP_WAIT(n)  asm volatile("cp.async.wait_group %0;" :: "n"(n) : "memory")

#define LDSM4(R, A)                                                          \
    asm volatile("ldmatrix.sync.aligned.m8n8.x4.shared.b16 {%0,%1,%2,%3}, [%4];" \
                 : "=r"((R)[0]), "=r"((R)[1]), "=r"((R)[2]), "=r"((R)[3]) : "r"(A))

#define MMA(C, A, B)                                                         \
    asm volatile("mma.sync.aligned.m16n8k16.row.col.f32.f16.f16.f32 "        \
                 "{%0,%1,%2,%3},{%4,%5,%6,%7},{%8,%9},{%0,%1,%2,%3};"        \
                 : "+f"((C)[0]), "+f"((C)[1]), "+f"((C)[2]), "+f"((C)[3])    \
                 : "r"((A)[0]), "r"((A)[1]), "r"((A)[2]), "r"((A)[3]),       \
                   "r"((B)[0]), "r"((B)[1]))

// ---------------------------------------------------------------------------
// W prep: Wt[n][k] = (fp16) W[k][n]. grid (60,4) block (32,8). Runs first.
// ---------------------------------------------------------------------------
__global__ __launch_bounds__(256) void wprep_kernel(const float* __restrict__ W)
{
    __shared__ float tile[32][33];
    int k0 = blockIdx.x * 32, n0 = blockIdx.y * 32;
    int x = threadIdx.x;
#pragma unroll
    for (int r = threadIdx.y; r < 32; r += 8)
        tile[r][x] = W[(size_t)(k0 + r) * On + n0 + x];
    __syncthreads();
#pragma unroll
    for (int r = threadIdx.y; r < 32; r += 8)
        g_Wt[(size_t)(n0 + r) * KC + k0 + x] = __float2half(tile[x][r]);
}

// ---------------------------------------------------------------------------
// Fused kernel: CTA owns queries [m0, m0+64).
//  Part 1 (per warp, 8 passes x 1 query): P[q,k,c] -> g_P (L2-hot), math
//    identical to the R11 champion (same fp32 fma order per (k,c)).
//  Part 2: out[m0:m0+64, :] = P @ Wt^T, R13 GEMM (8 warps, 16x64 warp tile,
//    BK=64, 2-stage cp.async) reading back the CTA's own L2-resident rows.
// ---------------------------------------------------------------------------
__device__ __forceinline__ void load_chunk(uint32_t sbase, int m0, int k0, int tid)
{
#pragma unroll
    for (int it = 0; it < 2; it++) {
        int idx = tid + it * 256;
        int r = idx >> 3, j = idx & 7;
        int gm = m0 + r;
        int ok = (gm < Qn);
        size_t go = (size_t)(ok ? gm : 0) * KC + k0 + j * 8;
        cp16(sbase + r * LDT + j * 16, g_P + go, ok ? 16 : 0);
    }
#pragma unroll
    for (int it = 0; it < 4; it++) {
        int idx = tid + it * 256;
        int r = idx >> 3, j = idx & 7;
        cp16(sbase + OFF_B + r * LDT + j * 16, g_Wt + (size_t)r * KC + k0 + j * 8, 16);
    }
}

__global__ __launch_bounds__(256, 2) void fused_kernel(
    const float* __restrict__ qpts, const float* __restrict__ feats,
    const float* __restrict__ kpts, const int* __restrict__ nbr,
    float* __restrict__ out)
{
    extern __shared__ char smem[];
    __shared__ float kp[Kn][3];

    const int tid = threadIdx.x;
    const int wid = tid >> 5;
    const int u   = tid & 31;
    const int m0  = blockIdx.x * BM;

    if (tid < Kn * 3) kp[tid / 3][tid % 3] = kpts[tid];
    __syncthreads();

    // ---------------- Part 1: per-warp P production ----------------
    {
        char* wb = smem + wid * P1_WARP_B;
        float  (*infl)[16]  = (float(*)[16])wb;            // [32][16]  2048 B
        float2 (*terms)[Hn] = (float2(*)[Hn])(wb + 2048);  // [15][32]  3840 B
        int*   rowB = (int*)(wb + 2048 + 3840);            // [32]       128 B
        int*   cnt  = (int*)(wb + 2048 + 3840 + 128);      // [15]        64 B

#pragma unroll 1
        for (int pass = 0; pass < 8; pass++) {
            int q = m0 + wid * 8 + pass;
            if (q >= Qn) break;

            // lane u = neighbor h
            int j = nbr[q * Hn + u];
            rowB[u] = j * Cn;
            float d0 = qpts[j * 3 + 0] - qpts[q * 3 + 0];
            float d1 = qpts[j * 3 + 1] - qpts[q * 3 + 1];
            float d2 = qpts[j * 3 + 2] - qpts[q * 3 + 2];

            // influences for this h (all 15 k)
#pragma unroll
            for (int k = 0; k < Kn; k++) {
                float dx = d0 - kp[k][0];
                float dy = d1 - kp[k][1];
                float dz = d2 - kp[k][2];
                float d  = sqrtf(fmaf(dx, dx, fmaf(dy, dy, dz * dz)));
                infl[u][k] = fmaxf(1.0f - d, 0.0f);
            }
            __syncwarp();

            // compact nonzero h-terms per k (lanes 0..14), h ascending
            if (u < Kn) {
                int n = 0;
#pragma unroll
                for (int h = 0; h < Hn; h++) {
                    float v = infl[h][u];
                    if (v > 0.0f) {
                        terms[u][n] = make_float2(v, __int_as_float(rowB[h]));
                        n++;
                    }
                }
                cnt[u] = n;
            }
            __syncwarp();

            // contraction: lane owns channels 4u..4u+3
            const int c = u * 4;
            size_t rowoff = (size_t)q * KC;
#pragma unroll
            for (int k = 0; k < Kn; k++) {
                float ax = 0.0f, ay = 0.0f, az = 0.0f, aw = 0.0f;
                int n = cnt[k];
                const float2* tl = terms[k];
                for (int t = 0; t < n; t++) {
                    float2 p = tl[t];
                    float4 f = *(const float4*)&feats[__float_as_int(p.y) + c];
                    ax = fmaf(p.x, f.x, ax);
                    ay = fmaf(p.x, f.y, ay);
                    az = fmaf(p.x, f.z, az);
                    aw = fmaf(p.x, f.w, aw);
                }
                __half2 lo = __floats2half2_rn(ax, ay);
                __half2 hi = __floats2half2_rn(az, aw);
                *(uint2*)&g_P[rowoff + k * Cn + c] =
                    make_uint2(*(uint32_t*)&lo, *(uint32_t*)&hi);
            }
            __syncwarp();
        }
    }
    __threadfence_block();
    __syncthreads();   // all P rows of this CTA written (visible at L2)

    // ---------------- Part 2: GEMM on own rows ----------------
    const uint32_t s0  = smem_u32(smem);
    const int lid = u;
    const int wm  = wid & 3;       // m slice (16 rows)
    const int wn  = wid >> 2;      // n half (64 cols)

    float acc[8][4];
#pragma unroll
    for (int b = 0; b < 8; b++)
#pragma unroll
        for (int c = 0; c < 4; c++) acc[b][c] = 0.0f;

    load_chunk(s0, m0, 0, tid);
    CP_COMMIT();

    for (int i = 0; i < NCH; i++) {
        if (i + 1 < NCH) {
            load_chunk(s0 + ((i + 1) & 1) * STAGE_B, m0, (i + 1) * BK, tid);
            CP_COMMIT();
            CP_WAIT(1);
        } else {
            CP_WAIT(0);
        }
        __syncthreads();

        const uint32_t sb = s0 + (i & 1) * STAGE_B;
#pragma unroll
        for (int kst = 0; kst < 4; kst++) {
            const uint32_t kb = kst * 32 + (lid >> 4) * 16;
            uint32_t af[4];
            {
                int row = wm * 16 + (lid & 15);
                LDSM4(af, sb + row * LDT + kb);
            }
            uint32_t bf[8][2];
#pragma unroll
            for (int p = 0; p < 4; p++) {
                int n = wn * 64 + p * 16 + (lid & 15);
                uint32_t r[4];
                LDSM4(r, sb + OFF_B + n * LDT + kb);
                bf[2 * p][0] = r[0];     bf[2 * p][1] = r[2];
                bf[2 * p + 1][0] = r[1]; bf[2 * p + 1][1] = r[3];
            }
#pragma unroll
            for (int nt = 0; nt < 8; nt++)
                MMA(acc[nt], af, bf[nt]);
        }
        __syncthreads();
    }

    // Epilogue: warp writes 16 rows x 64 cols
    int g = lid >> 2, tg = lid & 3;
    int r0 = m0 + wm * 16 + g;
#pragma unroll
    for (int nt = 0; nt < 8; nt++) {
        int col = wn * 64 + nt * 8 + 2 * tg;
        if (r0 < Qn)
            *(float2*)&out[(size_t)r0 * On + col] =
                make_float2(acc[nt][0], acc[nt][1]);
        if (r0 + 8 < Qn)
            *(float2*)&out[(size_t)(r0 + 8) * On + col] =
                make_float2(acc[nt][2], acc[nt][3]);
    }
}

// ---------------------------------------------------------------------------
// Launch
// ---------------------------------------------------------------------------
extern "C" void kernel_launch(void* const* d_in, const int* in_sizes, int n_in,
                              void* d_out, int out_size)
{
    const float* qpts  = 0;
    const float* feats = 0;
    const float* kpts  = 0;
    const float* W     = 0;
    const int*   nbr   = 0;

    for (int i = 0; i < n_in; i++) {
        int s = in_sizes[i];
        if      (s == Kn * 3)        { kpts  = (const float*)d_in[i]; }
        else if (s == Kn * Cn * On)  { W     = (const float*)d_in[i]; }
        else if (s == Qn * Hn)       { nbr   = (const int*)  d_in[i]; }
        else if (s == Gn * Cn)       { feats = (const float*)d_in[i]; }
        else if (s == Qn * 3)        { if (!qpts) qpts = (const float*)d_in[i]; }
    }
    if (!qpts || !feats || !kpts || !W || !nbr) {   // positional fallback
        qpts  = (const float*)d_in[0];
        feats = (const float*)d_in[2];
        kpts  = (const float*)d_in[3];
        W     = (const float*)d_in[4];
        nbr   = (const int*)  d_in[5];
    }
    float* out = (float*)d_out;

    static bool attr_set = false;
    if (!attr_set) {
        cudaFuncSetAttribute(fused_kernel,
                             cudaFuncAttributeMaxDynamicSharedMemorySize, SMEM_TOTAL);
        attr_set = true;
    }

    wprep_kernel<<<dim3(KC / 32, On / 32), dim3(32, 8)>>>(W);
    fused_kernel<<<(Qn + BM - 1) / BM, 256, SMEM_TOTAL>>>(qpts, feats, kpts, nbr, out);
}

// round 16
// speedup vs baseline: 1.6386x; 1.6386x over previous
#include <cuda_runtime.h>
#include <cuda_fp16.h>
#include <cstdint>

// Problem constants (fixed by the dataset)
#define Qn 20000
#define Gn 20000
#define Hn 32          // neighbors per query
#define Kn 15          // kernel points
#define Cn 128
#define On 128
#define KC (Kn * Cn)   // 1920

// Phase-2 GEMM tiling: 64x64 tiles -> 626 CTAs, ALL resident in one wave
#define BM 64
#define BN 64
#define BK 64
#define NCH (KC / BK)          // 30 chunks
#define LDT 144                // padded row stride in bytes (64 fp16 + 16B pad)
#define A_TILE_B (BM * LDT)    // 9216
#define B_TILE_B (BN * LDT)    // 9216
#define OFF_B    A_TILE_B
#define STAGE_B  (A_TILE_B + B_TILE_B)   // 18432
#define SMEM_TOTAL (2 * STAGE_B)          // 36864
#define MTILES ((Qn + BM - 1) / BM)       // 313

// Scratch (device globals per harness rules)
__device__ __align__(256) __half g_P [(size_t)Qn * KC];   // 76.8 MB
__device__ __align__(256) __half g_Wt[(size_t)On * KC];   // Wt[n][k], 4.9 MB

// ---------------------------------------------------------------------------
// PTX helpers (sm_80-era only: compile on base compute_103 target)
// ---------------------------------------------------------------------------
__device__ __forceinline__ uint32_t smem_u32(const void* p) {
    uint32_t a;
    asm("{ .reg .u64 t; cvta.to.shared.u64 t, %1; cvt.u32.u64 %0, t; }" : "=r"(a) : "l"(p));
    return a;
}
__device__ __forceinline__ void cp16(uint32_t dst, const void* src, int sz) {
    asm volatile("cp.async.cg.shared.global [%0], [%1], 16, %2;"
                 :: "r"(dst), "l"(src), "r"(sz) : "memory");
}
#define CP_COMMIT() asm volatile("cp.async.commit_group;" ::: "memory")
#define CP_WAIT(n)  asm volatile("cp.async.wait_group %0;" :: "n"(n) : "memory")

#define LDSM4(R, A)                                                          \
    asm volatile("ldmatrix.sync.aligned.m8n8.x4.shared.b16 {%0,%1,%2,%3}, [%4];" \
                 : "=r"((R)[0]), "=r"((R)[1]), "=r"((R)[2]), "=r"((R)[3]) : "r"(A))

#define MMA(C, A, B)                                                         \
    asm volatile("mma.sync.aligned.m16n8k16.row.col.f32.f16.f16.f32 "        \
                 "{%0,%1,%2,%3},{%4,%5,%6,%7},{%8,%9},{%0,%1,%2,%3};"        \
                 : "+f"((C)[0]), "+f"((C)[1]), "+f"((C)[2]), "+f"((C)[3])    \
                 : "r"((A)[0]), "r"((A)[1]), "r"((A)[2]), "r"((A)[3]),       \
                   "r"((B)[0]), "r"((B)[1]))

// ---------------------------------------------------------------------------
// Phase 1 (R11 champion, bit-exact): P[q,k,c] = sum_h relu(1-||d||)*feat -> fp16
// Block = 4 queries x 32 threads (1 warp per query); 4 channels/thread.
// ---------------------------------------------------------------------------
__global__ __launch_bounds__(128) void phase1_kernel(
    const float* __restrict__ qpts, const float* __restrict__ feats,
    const float* __restrict__ kpts, const int* __restrict__ nbr)
{
    const int tid = threadIdx.x;
    const int grp = tid >> 5;
    const int u   = tid & 31;
    const int qb  = blockIdx.x * 4;

    __shared__ float  infl[4][Hn][Kn + 1];
    __shared__ int    rowB[4][Hn];
    __shared__ float  dq[4][Hn][3];
    __shared__ float2 terms[4][Kn][Hn];
    __shared__ int    cnt[4][Kn];
    __shared__ float  kp[Kn][3];

    if (tid < Kn * 3)
        kp[tid / 3][tid % 3] = kpts[tid];

    {
        int q = qb + grp;
        int j = nbr[q * Hn + u];
        rowB[grp][u] = j * Cn;
        dq[grp][u][0] = qpts[j * 3 + 0] - qpts[q * 3 + 0];
        dq[grp][u][1] = qpts[j * 3 + 1] - qpts[q * 3 + 1];
        dq[grp][u][2] = qpts[j * 3 + 2] - qpts[q * 3 + 2];
    }
    __syncthreads();

#pragma unroll
    for (int it = 0; it < 15; it++) {
        int p  = tid + it * 128;
        int qq = p / (Hn * Kn);
        int r  = p % (Hn * Kn);
        int h  = r / Kn, k = r % Kn;
        float dx = dq[qq][h][0] - kp[k][0];
        float dy = dq[qq][h][1] - kp[k][1];
        float dz = dq[qq][h][2] - kp[k][2];
        float d  = sqrtf(fmaf(dx, dx, fmaf(dy, dy, dz * dz)));
        infl[qq][h][k] = fmaxf(1.0f - d, 0.0f);
    }
    __syncthreads();

    if (u < Kn) {
        int n = 0;
#pragma unroll
        for (int h = 0; h < Hn; h++) {
            float v = infl[grp][h][u];
            if (v > 0.0f) {
                terms[grp][u][n] = make_float2(v, __int_as_float(rowB[grp][h]));
                n++;
            }
        }
        cnt[grp][u] = n;
    }
    __syncthreads();

    const int c = u * 4;
    size_t rowoff = (size_t)(qb + grp) * KC;
#pragma unroll
    for (int k = 0; k < Kn; k++) {
        float ax = 0.0f, ay = 0.0f, az = 0.0f, aw = 0.0f;
        int n = cnt[grp][k];
        const float2* tl = terms[grp][k];
        for (int j = 0; j < n; j++) {
            float2 p = tl[j];
            float4 f = *(const float4*)&feats[__float_as_int(p.y) + c];
            ax = fmaf(p.x, f.x, ax);
            ay = fmaf(p.x, f.y, ay);
            az = fmaf(p.x, f.z, az);
            aw = fmaf(p.x, f.w, aw);
        }
        __half2 lo = __floats2half2_rn(ax, ay);
        __half2 hi = __floats2half2_rn(az, aw);
        *(uint2*)&g_P[rowoff + k * Cn + c] =
            make_uint2(*(uint32_t*)&lo, *(uint32_t*)&hi);
    }
}

// ---------------------------------------------------------------------------
// W prep: Wt[n][k] = (fp16) W[k][n]. grid (60,4) block (32,8).
// ---------------------------------------------------------------------------
__global__ __launch_bounds__(256) void wprep_kernel(const float* __restrict__ W)
{
    __shared__ float tile[32][33];
    int k0 = blockIdx.x * 32, n0 = blockIdx.y * 32;
    int x = threadIdx.x;
#pragma unroll
    for (int r = threadIdx.y; r < 32; r += 8)
        tile[r][x] = W[(size_t)(k0 + r) * On + n0 + x];
    __syncthreads();
#pragma unroll
    for (int r = threadIdx.y; r < 32; r += 8)
        g_Wt[(size_t)(n0 + r) * KC + k0 + x] = __float2half(tile[x][r]);
}

// ---------------------------------------------------------------------------
// Phase 2: out = P @ Wt^T via mma.sync fp16, fp32 accum.
// 64x64 CTA tile, 128 threads / 4 warps (warp tile 16x64), BK=64, 2-stage
// cp.async. Grid = 626 CTAs, all co-resident (kills the 2-wave tail).
// ---------------------------------------------------------------------------
__device__ __forceinline__ void load_chunk(uint32_t sbase, int m0, int n0,
                                           int k0, int tid)
{
    // A: 64 rows x 64 fp16 (512 x 16B, 4 iters of 128 threads)
#pragma unroll
    for (int it = 0; it < 4; it++) {
        int idx = tid + it * 128;
        int r = idx >> 3, j = idx & 7;
        int gm = m0 + r;
        int ok = (gm < Qn);
        size_t go = (size_t)(ok ? gm : 0) * KC + k0 + j * 8;
        cp16(sbase + r * LDT + j * 16, g_P + go, ok ? 16 : 0);
    }
    // B: 64 rows x 64 fp16 (512 x 16B, 4 iters)
#pragma unroll
    for (int it = 0; it < 4; it++) {
        int idx = tid + it * 128;
        int r = idx >> 3, j = idx & 7;
        cp16(sbase + OFF_B + r * LDT + j * 16,
             g_Wt + (size_t)(n0 + r) * KC + k0 + j * 8, 16);
    }
}

__global__ __launch_bounds__(128, 6) void phase2_mma(float* __restrict__ out)
{
    extern __shared__ char smem[];
    const uint32_t s0 = smem_u32(smem);
    const int tid = threadIdx.x;
    const int wid = tid >> 5;      // wm: 16-row slice
    const int lid = tid & 31;
    const int m0 = (blockIdx.x >> 1) * BM;
    const int n0 = (blockIdx.x & 1) * BN;

    float acc[8][4];
#pragma unroll
    for (int b = 0; b < 8; b++)
#pragma unroll
        for (int c = 0; c < 4; c++) acc[b][c] = 0.0f;

    load_chunk(s0, m0, n0, 0, tid);
    CP_COMMIT();

    for (int i = 0; i < NCH; i++) {
        if (i + 1 < NCH) {
            load_chunk(s0 + ((i + 1) & 1) * STAGE_B, m0, n0, (i + 1) * BK, tid);
            CP_COMMIT();
            CP_WAIT(1);
        } else {
            CP_WAIT(0);
        }
        __syncthreads();

        const uint32_t sb = s0 + (i & 1) * STAGE_B;
#pragma unroll
        for (int kst = 0; kst < 4; kst++) {
            const uint32_t kb = kst * 32 + (lid >> 4) * 16;
            uint32_t af[4];
            {
                int row = wid * 16 + (lid & 15);
                LDSM4(af, sb + row * LDT + kb);
            }
            uint32_t bf[8][2];
#pragma unroll
            for (int p = 0; p < 4; p++) {
                int n = p * 16 + (lid & 15);
                uint32_t r[4];
                LDSM4(r, sb + OFF_B + n * LDT + kb);
                bf[2 * p][0] = r[0];     bf[2 * p][1] = r[2];
                bf[2 * p + 1][0] = r[1]; bf[2 * p + 1][1] = r[3];
            }
#pragma unroll
            for (int nt = 0; nt < 8; nt++)
                MMA(acc[nt], af, bf[nt]);
        }
        __syncthreads();
    }

    // Epilogue: warp writes 16 rows x 64 cols
    int g = lid >> 2, tg = lid & 3;
    int r0 = m0 + wid * 16 + g;
#pragma unroll
    for (int nt = 0; nt < 8; nt++) {
        int col = n0 + nt * 8 + 2 * tg;
        if (r0 < Qn)
            *(float2*)&out[(size_t)r0 * On + col] =
                make_float2(acc[nt][0], acc[nt][1]);
        if (r0 + 8 < Qn)
            *(float2*)&out[(size_t)(r0 + 8) * On + col] =
                make_float2(acc[nt][2], acc[nt][3]);
    }
}

// ---------------------------------------------------------------------------
// Launch
// ---------------------------------------------------------------------------
extern "C" void kernel_launch(void* const* d_in, const int* in_sizes, int n_in,
                              void* d_out, int out_size)
{
    const float* qpts  = 0;
    const float* feats = 0;
    const float* kpts  = 0;
    const float* W     = 0;
    const int*   nbr   = 0;

    for (int i = 0; i < n_in; i++) {
        int s = in_sizes[i];
        if      (s == Kn * 3)        { kpts  = (const float*)d_in[i]; }
        else if (s == Kn * Cn * On)  { W     = (const float*)d_in[i]; }
        else if (s == Qn * Hn)       { nbr   = (const int*)  d_in[i]; }
        else if (s == Gn * Cn)       { feats = (const float*)d_in[i]; }
        else if (s == Qn * 3)        { if (!qpts) qpts = (const float*)d_in[i]; }
    }
    if (!qpts || !feats || !kpts || !W || !nbr) {   // positional fallback
        qpts  = (const float*)d_in[0];
        feats = (const float*)d_in[2];
        kpts  = (const float*)d_in[3];
        W     = (const float*)d_in[4];
        nbr   = (const int*)  d_in[5];
    }
    float* out = (float*)d_out;

    static bool attr_set = false;
    if (!attr_set) {
        cudaFuncSetAttribute(phase2_mma,
                             cudaFuncAttributeMaxDynamicSharedMemorySize, SMEM_TOTAL);
        attr_set = true;
    }

    phase1_kernel<<<Qn / 4, 128>>>(qpts, feats, kpts, nbr);
    wprep_kernel<<<dim3(KC / 32, On / 32), dim3(32, 8)>>>(W);
    phase2_mma<<<MTILES * 2, 128, SMEM_TOTAL>>>(out);
}